// round 11
// baseline (speedup 1.0000x reference)
#include <cuda_runtime.h>
#include <math.h>

#define B_ 16
#define HW 4096          // 64*64
#define CD 32
#define DIMX 512
#define NSCALES 14
#define NPIX (B_*HW)                 // 65536
#define OUT_ELEMS (B_*DIMX*HW)       // 33554432
#define POOL_FLOATS 898560           // float pools, scales 0..10

#define INV_SQRT32 0.17677669529663687f
#define ACOEF 70.710678118654755f    // 4*100/sqrt(32); p = sigmoid(-ACOEF*z)

__device__ float g_r0[NPIX*CD];      // original projection (token-major)
__device__ float g_r [NPIX*CD];      // residual (ping A)
__device__ float g_part[4][NPIX*CD]; // split-K partials; g_part[0] doubles as ping B
__device__ float g_pool[POOL_FLOATS];// pooled sums, scales 0..10
__device__ unsigned g_bits[57600];   // sign bitmaps: scale11 @0 (20736), scale12 @20736 (36864)
__device__ float g_acc[NSCALES][34]; // [0..31]=sum p, [32]=sum H, [33]=sum commit

__constant__ int c_ph[13]   = {1,2,3,4,5,7,9,12,16,21,27,36,48};
__constant__ int c_poff[11] = {0,512,2560,7168,15360,28160,53248,94720,
                               168448,299520,525312};

// ---------------------------------------------------------------- f32x2 helpers
__device__ __forceinline__ unsigned long long pk2(float x, float y) {
    unsigned long long r;
    asm("mov.b64 %0, {%1, %2};" : "=l"(r) : "f"(x), "f"(y));
    return r;
}
__device__ __forceinline__ unsigned long long fma2(unsigned long long a,
                                                   unsigned long long b,
                                                   unsigned long long c) {
    unsigned long long d;
    asm("fma.rn.f32x2 %0, %1, %2, %3;" : "=l"(d) : "l"(a), "l"(b), "l"(c));
    return d;
}
__device__ __forceinline__ void upk2(unsigned long long v, float& lo, float& hi) {
    asm("mov.b64 {%0, %1}, %2;" : "=f"(lo), "=f"(hi) : "l"(v));
}

// ---------------------------------------------------------------- init (every replay)
__global__ void init_kernel() {
    int t = blockIdx.x * blockDim.x + threadIdx.x;
    float4 z = make_float4(0.f, 0.f, 0.f, 0.f);
    for (int i = t; i < POOL_FLOATS / 4; i += gridDim.x * blockDim.x)
        ((float4*)g_pool)[i] = z;
    if (t < NSCALES * 34) ((float*)g_acc)[t] = 0.f;
}

// ---------------------------------------------------------------- proj_in GEMM (split-K=4, 2 px/thread)
__global__ __launch_bounds__(256) void gemm_in_kernel(
        const float* __restrict__ x, const float* __restrict__ w_in) {
    __shared__ float s_w[128 * CD];               // 16KB
    int tid = threadIdx.x;
    int kc = blockIdx.x & 3;
    int pg = blockIdx.x >> 2;                     // 0..127, 512 px each
    const float* wsrc = w_in + kc * 128 * CD;
    for (int i = tid; i < 128 * CD; i += 256) s_w[i] = wsrc[i];
    __syncthreads();

    int px0 = pg * 512 + tid, px1 = px0 + 256;
    int b = px0 >> 12;
    int pl0 = px0 & 4095, pl1 = px1 & 4095;
    const float* xb = x + (size_t)b * (DIMX * HW) + (size_t)(kc * 128) * HW;

    unsigned long long a0[16], a1[16];
#pragma unroll
    for (int i = 0; i < 16; i++) { a0[i] = 0ull; a1[i] = 0ull; }

#pragma unroll 2
    for (int c = 0; c < 128; c++) {
        float f0 = xb[(size_t)c * HW + pl0];
        float f1 = xb[(size_t)c * HW + pl1];
        unsigned long long X0 = pk2(f0, f0);
        unsigned long long X1 = pk2(f1, f1);
        const ulonglong2* row = (const ulonglong2*)(s_w + c * CD);
#pragma unroll
        for (int r = 0; r < 8; r++) {
            ulonglong2 w2 = row[r];
            a0[2*r]   = fma2(X0, w2.x, a0[2*r]);
            a0[2*r+1] = fma2(X0, w2.y, a0[2*r+1]);
            a1[2*r]   = fma2(X1, w2.x, a1[2*r]);
            a1[2*r+1] = fma2(X1, w2.y, a1[2*r+1]);
        }
    }
    ulonglong2* o0 = (ulonglong2*)(g_part[kc] + (size_t)px0 * CD);
    ulonglong2* o1 = (ulonglong2*)(g_part[kc] + (size_t)px1 * CD);
#pragma unroll
    for (int k = 0; k < 8; k++) {
        ulonglong2 v0; v0.x = a0[2*k]; v0.y = a0[2*k+1];
        ulonglong2 v1; v1.x = a1[2*k]; v1.y = a1[2*k+1];
        o0[k] = v0; o1[k] = v1;
    }
}

// combine: r0 = r = ((p0+p1)+(p2+p3)) + bias   (runs before g_part[0] reuse)
__global__ __launch_bounds__(256) void combine_kernel(const float* __restrict__ b_in) {
    int idx = blockIdx.x * 256 + threadIdx.x;   // float4 index, grid 2048
    float4 p0 = __ldg((const float4*)g_part[0] + idx);
    float4 p1 = __ldg((const float4*)g_part[1] + idx);
    float4 p2 = __ldg((const float4*)g_part[2] + idx);
    float4 p3 = __ldg((const float4*)g_part[3] + idx);
    float4 bi = __ldg((const float4*)b_in + (idx & 7));
    float4 v;
    v.x = (p0.x + p1.x) + (p2.x + p3.x) + bi.x;
    v.y = (p0.y + p1.y) + (p2.y + p3.y) + bi.y;
    v.z = (p0.z + p1.z) + (p2.z + p3.z) + bi.z;
    v.w = (p0.w + p1.w) + (p2.w + p3.w) + bi.w;
    ((float4*)g_r0)[idx] = v;
    ((float4*)g_r )[idx] = v;
}

// ---------------------------------------------------------------- per-token loss math (lane=d)
__device__ __forceinline__ void loss_token(float ir, float& pa, float& ha, float& ca) {
    float n2 = ir * ir;
#pragma unroll
    for (int o = 16; o > 0; o >>= 1) n2 += __shfl_xor_sync(~0u, n2, o);
    float z = ir / fmaxf(sqrtf(n2), 1e-12f);
    float p = 1.f / (1.f + expf(ACOEF * z));
    float H = -(p * logf(p + 1e-8f) + (1.f - p) * logf(1.f - p + 1e-8f));
    float qv = (z > 0.f) ? INV_SQRT32 : -INV_SQRT32;
    float dz = z - qv;
    pa += p; ha += H; ca += dz * dz;
}

// ---------------------------------------------------------------- pool (row x 16px chunks, atomic, MLP), s=0..10
__global__ __launch_bounds__(256) void pool_small_kernel(int s, int S, int Sx) {
    int tid = threadIdx.x, lane = tid & 31;
    int ph = c_ph[s], np = ph * ph, ntok = B_ * np;
    int base = c_poff[s];
    int w = blockIdx.x * 8 + (tid >> 5);
    if (w >= ntok * S * Sx) return;
    int tok = w / (S * Sx);
    int r2 = w - tok * (S * Sx);
    int sy = r2 / Sx, sx = r2 - sy * Sx;
    int b = tok / np, ij = tok - b * np, i = ij / ph, j = ij - i * ph;
    int sh = (i * 64) / ph, eh = ((i + 1) * 64 + ph - 1) / ph;
    int y = sh + sy;
    if (y >= eh) return;
    int sw = (j * 64) / ph, ew = ((j + 1) * 64 + ph - 1) / ph;
    int xs = sw + sx * 16;
    if (xs >= ew) return;
    int xe = min(ew, xs + 16);
    const float* row = g_r + ((size_t)(b * HW + y * 64)) * CD + lane;

    float s0 = 0.f, s1 = 0.f, s2 = 0.f, s3 = 0.f;
    int x = xs;
    for (; x + 8 <= xe; x += 8) {
        float a0 = row[(size_t)(x+0) * CD];
        float a1 = row[(size_t)(x+1) * CD];
        float a2 = row[(size_t)(x+2) * CD];
        float a3 = row[(size_t)(x+3) * CD];
        float a4 = row[(size_t)(x+4) * CD];
        float a5 = row[(size_t)(x+5) * CD];
        float a6 = row[(size_t)(x+6) * CD];
        float a7 = row[(size_t)(x+7) * CD];
        s0 += a0 + a4;
        s1 += a1 + a5;
        s2 += a2 + a6;
        s3 += a3 + a7;
    }
    for (; x < xe; x++) s0 += row[(size_t)x * CD];
    float sum = (s0 + s1) + (s2 + s3);
    atomicAdd(&g_pool[base + tok * CD + lane], sum);
}

// ---------------------------------------------------------------- up (pixel-parallel), s=0..9: float pools, fused loss(s)
// grid MUST be 2048 blocks; in-place on g_r
__global__ __launch_bounds__(256) void up_kernel(int s) {
    __shared__ int s_i0[64], s_i1[64];
    __shared__ float s_f[64];
    __shared__ float s_red[34];
    int tid = threadIdx.x, lane = tid & 31;
    int ph = c_ph[s], np = ph * ph;

    if (tid < 64) {
        float src = ((float)tid + 0.5f) * (float)ph * 0.015625f - 0.5f;
        src = fminf(fmaxf(src, 0.f), (float)(ph - 1));
        int i0 = (int)src;
        s_i0[tid] = i0;
        s_i1[tid] = min(i0 + 1, ph - 1);
        s_f[tid]  = src - (float)i0;
    }
    if (tid < 34) s_red[tid] = 0.f;
    __syncthreads();

    int gw = blockIdx.x * 8 + (tid >> 5);          // 16384 warps
    const float* pool = g_pool + c_poff[s];

    {   // loss(s): ntok(s<=9) <= 7056 <= 16384
        int ntok = B_ * np;
        if (gw < ntok) {
            int tok = gw;
            int b = tok / np, ij = tok - b * np, i = ij / ph, j = ij - i * ph;
            int ah = ((i + 1) * 64 + ph - 1) / ph - (i * 64) / ph;
            int aw = ((j + 1) * 64 + ph - 1) / ph - (j * 64) / ph;
            float ir = pool[tok * CD + lane] / (float)(ah * aw);
            float pa = 0.f, ha = 0.f, ca = 0.f;
            loss_token(ir, pa, ha, ca);
#pragma unroll
            for (int o = 16; o > 0; o >>= 1) {
                ha += __shfl_xor_sync(~0u, ha, o);
                ca += __shfl_xor_sync(~0u, ca, o);
            }
            atomicAdd(&s_red[lane], pa);
            if (lane == 0) { atomicAdd(&s_red[32], ha); atomicAdd(&s_red[33], ca); }
        }
    }

    int sub = lane >> 3, q = lane & 7;
    int px = gw * 4 + sub;
    int b = px >> 12, h = (px >> 6) & 63, w = px & 63;
    int i0 = s_i0[h], i1 = s_i1[h]; float fh = s_f[h];
    int j0 = s_i0[w], j1 = s_i1[w]; float fw = s_f[w];
    int tb = b * np;
    float4 p00 = *(const float4*)(pool + (tb + i0 * ph + j0) * CD + 4 * q);
    float4 p01 = *(const float4*)(pool + (tb + i0 * ph + j1) * CD + 4 * q);
    float4 p10 = *(const float4*)(pool + (tb + i1 * ph + j0) * CD + 4 * q);
    float4 p11 = *(const float4*)(pool + (tb + i1 * ph + j1) * CD + 4 * q);
    const float* a00 = (const float*)&p00;
    const float* a01 = (const float*)&p01;
    const float* a10 = (const float*)&p10;
    const float* a11 = (const float*)&p11;
    float v[4];
#pragma unroll
    for (int k = 0; k < 4; k++) {
        float s00 = a00[k] > 0.f ? 1.f : -1.f;
        float s01 = a01[k] > 0.f ? 1.f : -1.f;
        float s10 = a10[k] > 0.f ? 1.f : -1.f;
        float s11 = a11[k] > 0.f ? 1.f : -1.f;
        float top = s00 + fw * (s01 - s00);
        float bot = s10 + fw * (s11 - s10);
        v[k] = INV_SQRT32 * (top + fh * (bot - top));
    }
    float4* rp = (float4*)(g_r + (size_t)px * CD + 4 * q);
    float4 rv = *rp;
    rv.x -= v[0]; rv.y -= v[1]; rv.z -= v[2]; rv.w -= v[3];
    *rp = rv;

    __syncthreads();
    if (tid < 34) atomicAdd(&g_acc[s][tid], s_red[tid]);
}

// ---------------------------------------------------------------- fused up(s)+pool/bits(s+1)+loss(s+1), s in {10,11}
// grid = ceil(ntok(s+1)/8); warp owns one scale-(s+1) token; ping-pong rsrc->rdst
__global__ __launch_bounds__(256) void fused_kernel(int s, int flip) {
    __shared__ int s_i0[64], s_i1[64];
    __shared__ float s_f[64];
    __shared__ float s_redA[34];   // loss(s) when s==10
    __shared__ float s_redB[34];   // loss(s+1)
    int tid = threadIdx.x, lane = tid & 31;
    int ph = c_ph[s], np = ph * ph;
    int phn = c_ph[s + 1], npn = phn * phn;
    const float* rsrc = flip ? g_part[0] : g_r;
    float*       rdst = flip ? g_r : g_part[0];
    const bool use_bits = (s == 11);
    const float* poolS = g_pool + c_poff[10];        // only used when s==10
    const unsigned* bitsS = g_bits;                  // scale-11 bitmap (s==11)
    unsigned* bits_out = g_bits + (s == 10 ? 0 : 20736);

    if (tid < 64) {
        float src = ((float)tid + 0.5f) * (float)ph * 0.015625f - 0.5f;
        src = fminf(fmaxf(src, 0.f), (float)(ph - 1));
        int i0 = (int)src;
        s_i0[tid] = i0;
        s_i1[tid] = min(i0 + 1, ph - 1);
        s_f[tid]  = src - (float)i0;
    }
    if (tid < 34) { s_redA[tid] = 0.f; s_redB[tid] = 0.f; }
    __syncthreads();

    int gw = blockIdx.x * 8 + (tid >> 5);

    if (s == 10) {   // loss(10) from float pool[10]; ntok=11664 <= grid warps 20736
        int ntokS = B_ * np;
        if (gw < ntokS) {
            int tok = gw;
            int b = tok / np, ij = tok - b * np, i = ij / ph, j = ij - i * ph;
            int ah = ((i + 1) * 64 + ph - 1) / ph - (i * 64) / ph;
            int aw = ((j + 1) * 64 + ph - 1) / ph - (j * 64) / ph;
            float ir = poolS[tok * CD + lane] / (float)(ah * aw);
            float pa = 0.f, ha = 0.f, ca = 0.f;
            loss_token(ir, pa, ha, ca);
#pragma unroll
            for (int o = 16; o > 0; o >>= 1) {
                ha += __shfl_xor_sync(~0u, ha, o);
                ca += __shfl_xor_sync(~0u, ca, o);
            }
            atomicAdd(&s_redA[lane], pa);
            if (lane == 0) { atomicAdd(&s_redA[32], ha); atomicAdd(&s_redA[33], ca); }
        }
    }

    int sub = lane >> 3, q = lane & 7;
    int ntokn = B_ * npn;
    int t = gw;
    bool active = (t < ntokn);
    float4 acc = make_float4(0.f, 0.f, 0.f, 0.f);
    float inv_area = 1.f;

    if (active) {
        int b = t / npn, ij = t - b * npn, i = ij / phn, j = ij - i * phn;
        int sh = (i * 64) / phn, eh = ((i + 1) * 64 + phn - 1) / phn;
        int sw = (j * 64) / phn, ew = ((j + 1) * 64 + phn - 1) / phn;
        int sh2 = (i * 64 + phn - 1) / phn;      // owned partition start
        int sw2 = (j * 64 + phn - 1) / phn;
        int rh = eh - sh, rw = ew - sw;
        int npx = rh * rw;
        inv_area = 1.f / (float)npx;
        unsigned M = (65536u + (unsigned)rw - 1u) / (unsigned)rw;
        int iters = (npx + 3) >> 2;
        int tb = b * np;

        for (int it = 0; it < iters; it++) {
            int rp2 = it * 4 + sub;
            bool valid = rp2 < npx;
            int rpc = valid ? rp2 : 0;
            int dy = (int)(((unsigned)rpc * M) >> 16);
            int dx = rpc - dy * rw;
            int h = sh + dy, w2 = sw + dx;
            int px = (b << 12) + (h << 6) + w2;

            int i0 = s_i0[h], i1 = s_i1[h]; float fh = s_f[h];
            int j0 = s_i0[w2], j1 = s_i1[w2]; float fw = s_f[w2];
            int t00 = tb + i0 * ph + j0, t01 = tb + i0 * ph + j1;
            int t10 = tb + i1 * ph + j0, t11 = tb + i1 * ph + j1;

            float v[4];
            if (use_bits) {
                unsigned w00 = bitsS[t00], w01 = bitsS[t01];
                unsigned w10 = bitsS[t10], w11 = bitsS[t11];
#pragma unroll
                for (int k = 0; k < 4; k++) {
                    int d = 4 * q + k;
                    float s00 = ((w00 >> d) & 1u) ? 1.f : -1.f;
                    float s01 = ((w01 >> d) & 1u) ? 1.f : -1.f;
                    float s10 = ((w10 >> d) & 1u) ? 1.f : -1.f;
                    float s11 = ((w11 >> d) & 1u) ? 1.f : -1.f;
                    float top = s00 + fw * (s01 - s00);
                    float bot = s10 + fw * (s11 - s10);
                    v[k] = INV_SQRT32 * (top + fh * (bot - top));
                }
            } else {
                float4 p00 = *(const float4*)(poolS + t00 * CD + 4 * q);
                float4 p01 = *(const float4*)(poolS + t01 * CD + 4 * q);
                float4 p10 = *(const float4*)(poolS + t10 * CD + 4 * q);
                float4 p11 = *(const float4*)(poolS + t11 * CD + 4 * q);
                const float* a00 = (const float*)&p00;
                const float* a01 = (const float*)&p01;
                const float* a10 = (const float*)&p10;
                const float* a11 = (const float*)&p11;
#pragma unroll
                for (int k = 0; k < 4; k++) {
                    float s00 = a00[k] > 0.f ? 1.f : -1.f;
                    float s01 = a01[k] > 0.f ? 1.f : -1.f;
                    float s10 = a10[k] > 0.f ? 1.f : -1.f;
                    float s11 = a11[k] > 0.f ? 1.f : -1.f;
                    float top = s00 + fw * (s01 - s00);
                    float bot = s10 + fw * (s11 - s10);
                    v[k] = INV_SQRT32 * (top + fh * (bot - top));
                }
            }

            float4 rv = *(const float4*)(rsrc + (size_t)px * CD + 4 * q);
            rv.x -= v[0]; rv.y -= v[1]; rv.z -= v[2]; rv.w -= v[3];
            if (valid && h >= sh2 && w2 >= sw2)
                *(float4*)(rdst + (size_t)px * CD + 4 * q) = rv;
            if (valid) {
                acc.x += rv.x; acc.y += rv.y; acc.z += rv.z; acc.w += rv.w;
            }
        }
    }

    // deterministic cross-sub reduction
    acc.x += __shfl_xor_sync(~0u, acc.x, 8);  acc.x += __shfl_xor_sync(~0u, acc.x, 16);
    acc.y += __shfl_xor_sync(~0u, acc.y, 8);  acc.y += __shfl_xor_sync(~0u, acc.y, 16);
    acc.z += __shfl_xor_sync(~0u, acc.z, 8);  acc.z += __shfl_xor_sync(~0u, acc.z, 16);
    acc.w += __shfl_xor_sync(~0u, acc.w, 8);  acc.w += __shfl_xor_sync(~0u, acc.w, 16);

    unsigned nib = (acc.x > 0.f ? 1u : 0u) | (acc.y > 0.f ? 2u : 0u)
                 | (acc.z > 0.f ? 4u : 0u) | (acc.w > 0.f ? 8u : 0u);
    unsigned word = nib << (4 * q);
    word |= __shfl_xor_sync(~0u, word, 1);
    word |= __shfl_xor_sync(~0u, word, 2);
    word |= __shfl_xor_sync(~0u, word, 4);
    if (active && lane == 0) bits_out[t] = word;

    {   // loss(s+1) from pooled sums
        float irx = acc.x * inv_area, iry = acc.y * inv_area;
        float irz = acc.z * inv_area, irw = acc.w * inv_area;
        float n2 = irx*irx + iry*iry + irz*irz + irw*irw;
        n2 += __shfl_xor_sync(~0u, n2, 1);
        n2 += __shfl_xor_sync(~0u, n2, 2);
        n2 += __shfl_xor_sync(~0u, n2, 4);
        float inv = 1.f / fmaxf(sqrtf(n2), 1e-12f);
        float ir4[4] = {irx, iry, irz, irw};
        float pv[4], ha = 0.f, ca = 0.f;
#pragma unroll
        for (int k = 0; k < 4; k++) {
            float z = ir4[k] * inv;
            float p = 1.f / (1.f + expf(ACOEF * z));
            ha += -(p * logf(p + 1e-8f) + (1.f - p) * logf(1.f - p + 1e-8f));
            float qv = (z > 0.f) ? INV_SQRT32 : -INV_SQRT32;
            float dz = z - qv;
            ca += dz * dz;
            pv[k] = p;
        }
        ha += __shfl_xor_sync(~0u, ha, 1);
        ha += __shfl_xor_sync(~0u, ha, 2);
        ha += __shfl_xor_sync(~0u, ha, 4);
        ca += __shfl_xor_sync(~0u, ca, 1);
        ca += __shfl_xor_sync(~0u, ca, 2);
        ca += __shfl_xor_sync(~0u, ca, 4);
        if (active && sub == 0) {
            atomicAdd(&s_redB[4*q+0], pv[0]);
            atomicAdd(&s_redB[4*q+1], pv[1]);
            atomicAdd(&s_redB[4*q+2], pv[2]);
            atomicAdd(&s_redB[4*q+3], pv[3]);
            if (q == 0) { atomicAdd(&s_redB[32], ha); atomicAdd(&s_redB[33], ca); }
        }
    }

    __syncthreads();
    if (tid < 34) {
        atomicAdd(&g_acc[s + 1][tid], s_redB[tid]);
        if (s == 10) atomicAdd(&g_acc[10][tid], s_redA[tid]);
    }
}

// ---------------------------------------------------------------- up(12) + fused loss13; in-place on g_r
__global__ __launch_bounds__(256) void up12_kernel() {
    __shared__ int s_i0[64], s_i1[64];
    __shared__ float s_f[64];
    __shared__ float s_13[34];
    int tid = threadIdx.x, lane = tid & 31;
    const int ph = 48, np = 48 * 48;

    if (tid < 64) {
        float src = ((float)tid + 0.5f) * 48.f * 0.015625f - 0.5f;
        src = fminf(fmaxf(src, 0.f), 47.f);
        int i0 = (int)src;
        s_i0[tid] = i0;
        s_i1[tid] = min(i0 + 1, 47);
        s_f[tid]  = src - (float)i0;
    }
    if (tid < 34) s_13[tid] = 0.f;
    __syncthreads();

    int gw = blockIdx.x * 8 + (tid >> 5);
    int sub = lane >> 3, q = lane & 7;
    int px = gw * 4 + sub;
    int b = px >> 12, h = (px >> 6) & 63, w = px & 63;
    int i0 = s_i0[h], i1 = s_i1[h]; float fh = s_f[h];
    int j0 = s_i0[w], j1 = s_i1[w]; float fw = s_f[w];
    int tb = b * np;
    const unsigned* bits = g_bits + 20736;   // scale-12 bitmap
    unsigned w00 = bits[tb + i0 * ph + j0], w01 = bits[tb + i0 * ph + j1];
    unsigned w10 = bits[tb + i1 * ph + j0], w11 = bits[tb + i1 * ph + j1];

    float4* rp = (float4*)(g_r + (size_t)px * CD + 4 * q);
    float4 rv = *rp;
    float* rvp = (float*)&rv;
#pragma unroll
    for (int k = 0; k < 4; k++) {
        int d = 4 * q + k;
        float s00 = ((w00 >> d) & 1u) ? 1.f : -1.f;
        float s01 = ((w01 >> d) & 1u) ? 1.f : -1.f;
        float s10 = ((w10 >> d) & 1u) ? 1.f : -1.f;
        float s11 = ((w11 >> d) & 1u) ? 1.f : -1.f;
        float top = s00 + fw * (s01 - s00);
        float bot = s10 + fw * (s11 - s10);
        rvp[k] -= INV_SQRT32 * (top + fh * (bot - top));
    }
    *rp = rv;

    float n2 = rv.x*rv.x + rv.y*rv.y + rv.z*rv.z + rv.w*rv.w;
    n2 += __shfl_xor_sync(~0u, n2, 1);
    n2 += __shfl_xor_sync(~0u, n2, 2);
    n2 += __shfl_xor_sync(~0u, n2, 4);
    float inv = 1.f / fmaxf(sqrtf(n2), 1e-12f);
    float pv[4], ha = 0.f, ca = 0.f;
#pragma unroll
    for (int k = 0; k < 4; k++) {
        float z = rvp[k] * inv;
        float p = 1.f / (1.f + expf(ACOEF * z));
        ha += -(p * logf(p + 1e-8f) + (1.f - p) * logf(1.f - p + 1e-8f));
        float qv = (z > 0.f) ? INV_SQRT32 : -INV_SQRT32;
        float dz = z - qv;
        ca += dz * dz;
        pv[k] = p;
    }
    atomicAdd(&s_13[4*q+0], pv[0]);
    atomicAdd(&s_13[4*q+1], pv[1]);
    atomicAdd(&s_13[4*q+2], pv[2]);
    atomicAdd(&s_13[4*q+3], pv[3]);
#pragma unroll
    for (int o = 16; o > 0; o >>= 1) {
        ha += __shfl_xor_sync(~0u, ha, o);
        ca += __shfl_xor_sync(~0u, ca, o);
    }
    if (lane == 0) { atomicAdd(&s_13[32], ha); atomicAdd(&s_13[33], ca); }

    __syncthreads();
    if (tid < 34) atomicAdd(&g_acc[13][tid], s_13[tid]);
}

// ---------------------------------------------------------------- finalize losses
__global__ void finalize_kernel(float* __restrict__ loss_out) {
    int s = threadIdx.x >> 5;
    int lane = threadIdx.x & 31;
    if (s >= NSCALES) return;
    int ph = (s < 13) ? c_ph[s] : 64;
    float n = (float)(B_ * ph * ph);
    float ap = g_acc[s][lane] / n;
    float H = -(ap * logf(ap + 1e-8f) + (1.f - ap) * logf(1.f - ap + 1e-8f));
#pragma unroll
    for (int o = 16; o > 0; o >>= 1) H += __shfl_xor_sync(~0u, H, o);
    if (lane == 0) {
        float ps = g_acc[s][32] / n;
        float cm = g_acc[s][33] / (n * 32.f);
        loss_out[s] = (ps - H) * (0.1f / 100.f) + 0.25f * cm;
    }
}

// ---------------------------------------------------------------- proj_out GEMM (split-N=4, 2 px/thread)
__global__ __launch_bounds__(256) void gemm_out_kernel(
        const float* __restrict__ w_out,
        const float* __restrict__ b_out,
        float* __restrict__ out) {
    __shared__ float s_wt[128 * 36];    // padded transpose [c][d], 18KB
    __shared__ float s_b[128];
    int tid = threadIdx.x;
    int kc = blockIdx.x & 3;
    int pg = blockIdx.x >> 2;           // 0..127, 512 px each
    int c0 = kc * 128;
    for (int i = tid; i < 128 * CD; i += 256) {
        int d = i >> 7, c = i & 127;
        s_wt[c * 36 + d] = w_out[d * DIMX + c0 + c];
    }
    if (tid < 128) s_b[tid] = b_out[c0 + tid];
    __syncthreads();

    int px0 = pg * 512 + tid, px1 = px0 + 256;
    int b = px0 >> 12;
    int pl0 = px0 & 4095, pl1 = px1 & 4095;
    size_t o0 = (size_t)px0 * CD, o1 = (size_t)px1 * CD;

    unsigned long long Q0[16], Q1[16];
#pragma unroll
    for (int k = 0; k < 8; k++) {
        float4 a = __ldg((const float4*)(g_r0 + o0) + k);
        float4 r = ((const float4*)(g_r + o0))[k];
        float qx = (r.x > 0.f) ? INV_SQRT32 : -INV_SQRT32;
        float qy = (r.y > 0.f) ? INV_SQRT32 : -INV_SQRT32;
        float qz = (r.z > 0.f) ? INV_SQRT32 : -INV_SQRT32;
        float qw = (r.w > 0.f) ? INV_SQRT32 : -INV_SQRT32;
        Q0[2*k]   = pk2(a.x - r.x + qx, a.y - r.y + qy);
        Q0[2*k+1] = pk2(a.z - r.z + qz, a.w - r.w + qw);
        float4 a1 = __ldg((const float4*)(g_r0 + o1) + k);
        float4 r1 = ((const float4*)(g_r + o1))[k];
        qx = (r1.x > 0.f) ? INV_SQRT32 : -INV_SQRT32;
        qy = (r1.y > 0.f) ? INV_SQRT32 : -INV_SQRT32;
        qz = (r1.z > 0.f) ? INV_SQRT32 : -INV_SQRT32;
        qw = (r1.w > 0.f) ? INV_SQRT32 : -INV_SQRT32;
        Q1[2*k]   = pk2(a1.x - r1.x + qx, a1.y - r1.y + qy);
        Q1[2*k+1] = pk2(a1.z - r1.z + qz, a1.w - r1.w + qw);
    }

    float* opb = out + (size_t)b * (DIMX * HW) + (size_t)c0 * HW;
#pragma unroll 2
    for (int c = 0; c < 128; c++) {
        const ulonglong2* wrow = (const ulonglong2*)(s_wt + c * 36);
        unsigned long long ae0 = 0, ao0 = 0, ae1 = 0, ao1 = 0;
#pragma unroll
        for (int r = 0; r < 8; r++) {
            ulonglong2 W = wrow[r];
            ae0 = fma2(Q0[2*r],   W.x, ae0);
            ao0 = fma2(Q0[2*r+1], W.y, ao0);
            ae1 = fma2(Q1[2*r],   W.x, ae1);
            ao1 = fma2(Q1[2*r+1], W.y, ao1);
        }
        float lo, hi, sum0, sum1;
        upk2(ae0, lo, hi); sum0 = lo + hi;
        upk2(ao0, lo, hi); sum0 += lo + hi;
        upk2(ae1, lo, hi); sum1 = lo + hi;
        upk2(ao1, lo, hi); sum1 += lo + hi;
        float bias = s_b[c];
        opb[(size_t)c * HW + pl0] = sum0 + bias;
        opb[(size_t)c * HW + pl1] = sum1 + bias;
    }
}

// ---------------------------------------------------------------- launch
extern "C" void kernel_launch(void* const* d_in, const int* in_sizes, int n_in,
                              void* d_out, int out_size) {
    const float* x     = (const float*)d_in[0];
    const float* w_in  = (const float*)d_in[1];
    const float* b_in  = (const float*)d_in[2];
    const float* w_out = (const float*)d_in[3];
    const float* b_out = (const float*)d_in[4];
    float* out = (float*)d_out;

    static const int sched[13] = {1,2,3,4,5,7,9,12,16,21,27,36,48};
    static const int SxT[11]   = {4,2,2,1,1,1,1,1,1,1,1};

    init_kernel<<<1024, 256>>>();
    gemm_in_kernel<<<512, 256>>>(x, w_in);
    combine_kernel<<<2048, 256>>>(b_in);

    // s = 0..9: atomic float pool + pixel-parallel up (in-place on g_r)
    for (int s = 0; s < 10; s++) {
        int ph = sched[s];
        int ntok = B_ * ph * ph;
        int S = 64 / ph + 2;
        int Sx = SxT[s];
        int work = ntok * S * Sx;
        pool_small_kernel<<<(work + 7) / 8, 256>>>(s, S, Sx);
        up_kernel<<<2048, 256>>>(s);
    }
    // pool(10), then fused chain s=10,11 (ping-pong g_r <-> g_part[0]), then up12
    {
        int ph = 27, ntok = B_ * ph * ph;
        int S = 64 / ph + 2;
        int work = ntok * S;
        pool_small_kernel<<<(work + 7) / 8, 256>>>(10, S, 1);
    }
    fused_kernel<<<(B_ * 36 * 36 + 7) / 8, 256>>>(10, 0);   // g_r -> g_part[0]
    fused_kernel<<<(B_ * 48 * 48 + 7) / 8, 256>>>(11, 1);   // g_part[0] -> g_r
    up12_kernel<<<2048, 256>>>();

    if (out_size >= OUT_ELEMS + NSCALES)
        finalize_kernel<<<1, NSCALES * 32>>>(out + OUT_ELEMS);
    gemm_out_kernel<<<512, 256>>>(w_out, b_out, out);
}

// round 12
// speedup vs baseline: 1.0980x; 1.0980x over previous
#include <cuda_runtime.h>
#include <math.h>

#define B_ 16
#define HW 4096          // 64*64
#define CD 32
#define DIMX 512
#define NSCALES 14
#define NPIX (B_*HW)                 // 65536
#define OUT_ELEMS (B_*DIMX*HW)       // 33554432

#define INV_SQRT32 0.17677669529663687f
#define ACOEF 70.710678118654755f    // 4*100/sqrt(32); p = sigmoid(-ACOEF*z)

__device__ float g_r0[NPIX*CD];      // original projection (token-major)
__device__ float g_r [NPIX*CD];      // residual
__device__ float g_part[4][NPIX*CD]; // split-K partials for proj_in
__device__ float g_pool[94720];      // pooled sums, sliced scales 0..6 only
__device__ unsigned g_bits[82720];   // sign bitmaps, scales 7..12
__device__ float g_acc[NSCALES][34]; // [0..31]=sum p, [32]=sum H, [33]=sum commit

__constant__ int c_ph[13]   = {1,2,3,4,5,7,9,12,16,21,27,36,48};
__constant__ int c_poff[7]  = {0,512,2560,7168,15360,28160,53248};    // float pools s<7
__constant__ int c_boff[13] = {0,0,0,0,0,0,0, 0,2304,6400,13456,25120,45856}; // bitmaps s>=7
#define SLICED_POOL_FLOATS 94720

// ---------------------------------------------------------------- f32x2 helpers
__device__ __forceinline__ unsigned long long pk2(float x, float y) {
    unsigned long long r;
    asm("mov.b64 %0, {%1, %2};" : "=l"(r) : "f"(x), "f"(y));
    return r;
}
__device__ __forceinline__ unsigned long long fma2(unsigned long long a,
                                                   unsigned long long b,
                                                   unsigned long long c) {
    unsigned long long d;
    asm("fma.rn.f32x2 %0, %1, %2, %3;" : "=l"(d) : "l"(a), "l"(b), "l"(c));
    return d;
}
__device__ __forceinline__ void upk2(unsigned long long v, float& lo, float& hi) {
    asm("mov.b64 {%0, %1}, %2;" : "=f"(lo), "=f"(hi) : "l"(v));
}

// ---------------------------------------------------------------- init (every replay)
__global__ void init_kernel() {
    int t = blockIdx.x * blockDim.x + threadIdx.x;
    for (int i = t; i < SLICED_POOL_FLOATS; i += gridDim.x * blockDim.x)
        g_pool[i] = 0.f;
    if (t < NSCALES * 34) ((float*)g_acc)[t] = 0.f;
}

// ---------------------------------------------------------------- proj_in GEMM (split-K=4, 1 px/thread)
__global__ __launch_bounds__(256) void gemm_in_kernel(
        const float* __restrict__ x, const float* __restrict__ w_in) {
    __shared__ float s_w[128 * CD];
    int tid = threadIdx.x;
    int kc = blockIdx.x & 3;
    int pg = blockIdx.x >> 2;
    const float* wsrc = w_in + kc * 128 * CD;
    for (int i = tid; i < 128 * CD; i += 256) s_w[i] = wsrc[i];
    __syncthreads();

    int px = pg * 256 + tid;
    int b = px >> 12, pl = px & 4095;
    const float* xp = x + (size_t)b * (DIMX * HW) + (size_t)(kc * 128) * HW + pl;

    unsigned long long a[16];
#pragma unroll
    for (int i = 0; i < 16; i++) a[i] = 0ull;

#pragma unroll 4
    for (int c = 0; c < 128; c++) {
        float f = xp[(size_t)c * HW];
        unsigned long long X = pk2(f, f);
        const ulonglong2* row = (const ulonglong2*)(s_w + c * CD);
#pragma unroll
        for (int r = 0; r < 8; r++) {
            ulonglong2 w2 = row[r];
            a[2*r]   = fma2(X, w2.x, a[2*r]);
            a[2*r+1] = fma2(X, w2.y, a[2*r+1]);
        }
    }
    ulonglong2* o = (ulonglong2*)(g_part[kc] + (size_t)px * CD);
#pragma unroll
    for (int k = 0; k < 8; k++) {
        ulonglong2 v; v.x = a[2*k]; v.y = a[2*k+1];
        o[k] = v;
    }
}

// combine: r0 = r = ((p0+p1)+(p2+p3)) + bias
__global__ __launch_bounds__(256) void combine_kernel(const float* __restrict__ b_in) {
    int idx = blockIdx.x * 256 + threadIdx.x;   // float4 index, grid 2048
    float4 p0 = __ldg((const float4*)g_part[0] + idx);
    float4 p1 = __ldg((const float4*)g_part[1] + idx);
    float4 p2 = __ldg((const float4*)g_part[2] + idx);
    float4 p3 = __ldg((const float4*)g_part[3] + idx);
    float4 bi = __ldg((const float4*)b_in + (idx & 7));
    float4 v;
    v.x = (p0.x + p1.x) + (p2.x + p3.x) + bi.x;
    v.y = (p0.y + p1.y) + (p2.y + p3.y) + bi.y;
    v.z = (p0.z + p1.z) + (p2.z + p3.z) + bi.z;
    v.w = (p0.w + p1.w) + (p2.w + p3.w) + bi.w;
    ((float4*)g_r0)[idx] = v;
    ((float4*)g_r )[idx] = v;
}

// ---------------------------------------------------------------- per-token loss math (lane=d)
__device__ __forceinline__ void loss_token(float ir, float& pa, float& ha, float& ca) {
    float n2 = ir * ir;
#pragma unroll
    for (int o = 16; o > 0; o >>= 1) n2 += __shfl_xor_sync(~0u, n2, o);
    float z = ir / fmaxf(sqrtf(n2), 1e-12f);
    float p = 1.f / (1.f + expf(ACOEF * z));
    float H = -(p * logf(p + 1e-8f) + (1.f - p) * logf(1.f - p + 1e-8f));
    float qv = (z > 0.f) ? INV_SQRT32 : -INV_SQRT32;
    float dz = z - qv;
    pa += p; ha += H; ca += dz * dz;
}

// ---------------------------------------------------------------- pool, big scales (warp/token, fused loss, sign bitmap out)
__global__ __launch_bounds__(256) void pool_big_kernel(int s) {
    __shared__ float s_red[34];
    int tid = threadIdx.x, lane = tid & 31;
    if (tid < 34) s_red[tid] = 0.f;
    __syncthreads();

    int ph = c_ph[s], np = ph * ph, ntok = B_ * np;
    unsigned* bits = g_bits + c_boff[s];
    int gw = blockIdx.x * 8 + (tid >> 5);
    int nw = gridDim.x * 8;

    float pa = 0.f, ha = 0.f, ca = 0.f;
    for (int tok = gw; tok < ntok; tok += nw) {
        int b = tok / np, ij = tok - b * np, i = ij / ph, j = ij - i * ph;
        int sh = (i * 64) / ph, eh = ((i + 1) * 64 + ph - 1) / ph;
        int sw = (j * 64) / ph, ew = ((j + 1) * 64 + ph - 1) / ph;
        const float* rb = g_r + ((size_t)(b * HW)) * CD + lane;
        float sum = 0.f;
        for (int y = sh; y < eh; y++) {
            const float* row = rb + (size_t)(y * 64) * CD;
#pragma unroll 2
            for (int x = sw; x < ew; x++) sum += row[(size_t)x * CD];
        }
        unsigned word = __ballot_sync(~0u, sum > 0.f);
        if (lane == 0) bits[tok] = word;
        loss_token(sum / (float)((eh - sh) * (ew - sw)), pa, ha, ca);
    }
#pragma unroll
    for (int o = 16; o > 0; o >>= 1) {
        ha += __shfl_xor_sync(~0u, ha, o);
        ca += __shfl_xor_sync(~0u, ca, o);
    }
    atomicAdd(&s_red[lane], pa);
    if (lane == 0) { atomicAdd(&s_red[32], ha); atomicAdd(&s_red[33], ca); }
    __syncthreads();
    if (tid < 34) atomicAdd(&g_acc[s][tid], s_red[tid]);
}

// ---------------------------------------------------------------- pool, small scales (row x 16px chunks, atomic, deep MLP)
__global__ __launch_bounds__(256) void pool_small_kernel(int s, int S, int Sx) {
    int tid = threadIdx.x, lane = tid & 31;
    int ph = c_ph[s], np = ph * ph, ntok = B_ * np;
    int base = c_poff[s];
    int w = blockIdx.x * 8 + (tid >> 5);
    if (w >= ntok * S * Sx) return;
    int tok = w / (S * Sx);
    int r2 = w - tok * (S * Sx);
    int sy = r2 / Sx, sx = r2 - sy * Sx;
    int b = tok / np, ij = tok - b * np, i = ij / ph, j = ij - i * ph;
    int sh = (i * 64) / ph, eh = ((i + 1) * 64 + ph - 1) / ph;
    int y = sh + sy;
    if (y >= eh) return;
    int sw = (j * 64) / ph, ew = ((j + 1) * 64 + ph - 1) / ph;
    int xs = sw + sx * 16;
    if (xs >= ew) return;
    int xe = min(ew, xs + 16);
    const float* row = g_r + ((size_t)(b * HW + y * 64)) * CD + lane;

    float s0 = 0.f, s1 = 0.f, s2 = 0.f, s3 = 0.f;
    int x = xs;
    for (; x + 8 <= xe; x += 8) {
        float a0 = row[(size_t)(x+0) * CD];
        float a1 = row[(size_t)(x+1) * CD];
        float a2 = row[(size_t)(x+2) * CD];
        float a3 = row[(size_t)(x+3) * CD];
        float a4 = row[(size_t)(x+4) * CD];
        float a5 = row[(size_t)(x+5) * CD];
        float a6 = row[(size_t)(x+6) * CD];
        float a7 = row[(size_t)(x+7) * CD];
        s0 += a0 + a4;
        s1 += a1 + a5;
        s2 += a2 + a6;
        s3 += a3 + a7;
    }
    for (; x < xe; x++) s0 += row[(size_t)x * CD];
    float sum = (s0 + s1) + (s2 + s3);
    atomicAdd(&g_pool[base + tok * CD + lane], sum);
}

// ---------------------------------------------------------------- up: r -= bilerp(sign); 4 px/warp; fused loss for sliced scales
// grid MUST be 2048 blocks; s = 0..11 (s=12 handled by up12_kernel)
__global__ __launch_bounds__(256) void up_kernel(int s, int sliced) {
    __shared__ int s_i0[64], s_i1[64];
    __shared__ float s_f[64];
    __shared__ float s_red[34];
    int tid = threadIdx.x, lane = tid & 31;
    int ph = c_ph[s], np = ph * ph;

    if (tid < 64) {
        float src = ((float)tid + 0.5f) * (float)ph * 0.015625f - 0.5f;
        src = fminf(fmaxf(src, 0.f), (float)(ph - 1));
        int i0 = (int)src;
        s_i0[tid] = i0;
        s_i1[tid] = min(i0 + 1, ph - 1);
        s_f[tid]  = src - (float)i0;
    }
    if (tid < 34) s_red[tid] = 0.f;
    __syncthreads();

    int gw = blockIdx.x * 8 + (tid >> 5);          // 16384 warps total

    if (sliced) {
        int ntok = B_ * np;
        if (gw < ntok) {
            const float* pool = g_pool + c_poff[s];
            int tok = gw;
            int b = tok / np, ij = tok - b * np, i = ij / ph, j = ij - i * ph;
            int ah = ((i + 1) * 64 + ph - 1) / ph - (i * 64) / ph;
            int aw = ((j + 1) * 64 + ph - 1) / ph - (j * 64) / ph;
            float ir = pool[tok * CD + lane] / (float)(ah * aw);
            float pa = 0.f, ha = 0.f, ca = 0.f;
            loss_token(ir, pa, ha, ca);
#pragma unroll
            for (int o = 16; o > 0; o >>= 1) {
                ha += __shfl_xor_sync(~0u, ha, o);
                ca += __shfl_xor_sync(~0u, ca, o);
            }
            atomicAdd(&s_red[lane], pa);
            if (lane == 0) { atomicAdd(&s_red[32], ha); atomicAdd(&s_red[33], ca); }
        }
    }

    // pixel work: lane = sub(2b) * 8 + q(3b); px = gw*4+sub, d = 4q..4q+3
    int sub = lane >> 3, q = lane & 7;
    int px = gw * 4 + sub;
    int b = px >> 12, h = (px >> 6) & 63, w = px & 63;
    int i0 = s_i0[h], i1 = s_i1[h]; float fh = s_f[h];
    int j0 = s_i0[w], j1 = s_i1[w]; float fw = s_f[w];
    int tb = b * np;
    int t00 = tb + i0 * ph + j0, t01 = tb + i0 * ph + j1;
    int t10 = tb + i1 * ph + j0, t11 = tb + i1 * ph + j1;

    float v[4];
    if (s >= 7) {
        const unsigned* bits = g_bits + c_boff[s];
        unsigned w00 = bits[t00], w01 = bits[t01];
        unsigned w10 = bits[t10], w11 = bits[t11];
#pragma unroll
        for (int k = 0; k < 4; k++) {
            int d = 4 * q + k;
            float s00 = ((w00 >> d) & 1u) ? 1.f : -1.f;
            float s01 = ((w01 >> d) & 1u) ? 1.f : -1.f;
            float s10 = ((w10 >> d) & 1u) ? 1.f : -1.f;
            float s11 = ((w11 >> d) & 1u) ? 1.f : -1.f;
            float top = s00 + fw * (s01 - s00);
            float bot = s10 + fw * (s11 - s10);
            v[k] = INV_SQRT32 * (top + fh * (bot - top));
        }
    } else {
        const float* pool = g_pool + c_poff[s];
        float4 p00 = *(const float4*)(pool + t00 * CD + 4 * q);
        float4 p01 = *(const float4*)(pool + t01 * CD + 4 * q);
        float4 p10 = *(const float4*)(pool + t10 * CD + 4 * q);
        float4 p11 = *(const float4*)(pool + t11 * CD + 4 * q);
        const float* a00 = (const float*)&p00;
        const float* a01 = (const float*)&p01;
        const float* a10 = (const float*)&p10;
        const float* a11 = (const float*)&p11;
#pragma unroll
        for (int k = 0; k < 4; k++) {
            float s00 = a00[k] > 0.f ? 1.f : -1.f;
            float s01 = a01[k] > 0.f ? 1.f : -1.f;
            float s10 = a10[k] > 0.f ? 1.f : -1.f;
            float s11 = a11[k] > 0.f ? 1.f : -1.f;
            float top = s00 + fw * (s01 - s00);
            float bot = s10 + fw * (s11 - s10);
            v[k] = INV_SQRT32 * (top + fh * (bot - top));
        }
    }

    float4* rp = (float4*)(g_r + (size_t)px * CD + 4 * q);
    float4 rv = *rp;
    rv.x -= v[0]; rv.y -= v[1]; rv.z -= v[2]; rv.w -= v[3];
    *rp = rv;

    if (sliced) {
        __syncthreads();
        if (tid < 34) atomicAdd(&g_acc[s][tid], s_red[tid]);
    }
}

// ---------------------------------------------------------------- up(12) + fused loss13; in-place on g_r (grid 2048)
__global__ __launch_bounds__(256) void up12_kernel() {
    __shared__ int s_i0[64], s_i1[64];
    __shared__ float s_f[64];
    __shared__ float s_13[34];
    int tid = threadIdx.x, lane = tid & 31;
    const int ph = 48, np = 48 * 48;

    if (tid < 64) {
        float src = ((float)tid + 0.5f) * 48.f * 0.015625f - 0.5f;
        src = fminf(fmaxf(src, 0.f), 47.f);
        int i0 = (int)src;
        s_i0[tid] = i0;
        s_i1[tid] = min(i0 + 1, 47);
        s_f[tid]  = src - (float)i0;
    }
    if (tid < 34) s_13[tid] = 0.f;
    __syncthreads();

    int gw = blockIdx.x * 8 + (tid >> 5);
    int sub = lane >> 3, q = lane & 7;
    int px = gw * 4 + sub;
    int b = px >> 12, h = (px >> 6) & 63, w = px & 63;
    int i0 = s_i0[h], i1 = s_i1[h]; float fh = s_f[h];
    int j0 = s_i0[w], j1 = s_i1[w]; float fw = s_f[w];
    int tb = b * np;
    const unsigned* bits = g_bits + 45856;   // scale-12 bitmap
    unsigned w00 = bits[tb + i0 * ph + j0], w01 = bits[tb + i0 * ph + j1];
    unsigned w10 = bits[tb + i1 * ph + j0], w11 = bits[tb + i1 * ph + j1];

    float4* rp = (float4*)(g_r + (size_t)px * CD + 4 * q);
    float4 rv = *rp;
    float* rvp = (float*)&rv;
#pragma unroll
    for (int k = 0; k < 4; k++) {
        int d = 4 * q + k;
        float s00 = ((w00 >> d) & 1u) ? 1.f : -1.f;
        float s01 = ((w01 >> d) & 1u) ? 1.f : -1.f;
        float s10 = ((w10 >> d) & 1u) ? 1.f : -1.f;
        float s11 = ((w11 >> d) & 1u) ? 1.f : -1.f;
        float top = s00 + fw * (s01 - s00);
        float bot = s10 + fw * (s11 - s10);
        rvp[k] -= INV_SQRT32 * (top + fh * (bot - top));
    }
    *rp = rv;

    // fused loss13 (identity tokens = pixels) on new residuals
    float n2 = rv.x*rv.x + rv.y*rv.y + rv.z*rv.z + rv.w*rv.w;
    n2 += __shfl_xor_sync(~0u, n2, 1);
    n2 += __shfl_xor_sync(~0u, n2, 2);
    n2 += __shfl_xor_sync(~0u, n2, 4);
    float inv = 1.f / fmaxf(sqrtf(n2), 1e-12f);
    float pv[4], ha = 0.f, ca = 0.f;
#pragma unroll
    for (int k = 0; k < 4; k++) {
        float z = rvp[k] * inv;
        float p = 1.f / (1.f + expf(ACOEF * z));
        ha += -(p * logf(p + 1e-8f) + (1.f - p) * logf(1.f - p + 1e-8f));
        float qv = (z > 0.f) ? INV_SQRT32 : -INV_SQRT32;
        float dz = z - qv;
        ca += dz * dz;
        pv[k] = p;
    }
    atomicAdd(&s_13[4*q+0], pv[0]);
    atomicAdd(&s_13[4*q+1], pv[1]);
    atomicAdd(&s_13[4*q+2], pv[2]);
    atomicAdd(&s_13[4*q+3], pv[3]);
#pragma unroll
    for (int o = 16; o > 0; o >>= 1) {
        ha += __shfl_xor_sync(~0u, ha, o);
        ca += __shfl_xor_sync(~0u, ca, o);
    }
    if (lane == 0) { atomicAdd(&s_13[32], ha); atomicAdd(&s_13[33], ca); }

    __syncthreads();
    if (tid < 34) atomicAdd(&g_acc[13][tid], s_13[tid]);
}

// ---------------------------------------------------------------- finalize losses
__global__ void finalize_kernel(float* __restrict__ loss_out) {
    int s = threadIdx.x >> 5;
    int lane = threadIdx.x & 31;
    if (s >= NSCALES) return;
    int ph = (s < 13) ? c_ph[s] : 64;
    float n = (float)(B_ * ph * ph);
    float ap = g_acc[s][lane] / n;
    float H = -(ap * logf(ap + 1e-8f) + (1.f - ap) * logf(1.f - ap + 1e-8f));
#pragma unroll
    for (int o = 16; o > 0; o >>= 1) H += __shfl_xor_sync(~0u, H, o);
    if (lane == 0) {
        float ps = g_acc[s][32] / n;
        float cm = g_acc[s][33] / (n * 32.f);
        loss_out[s] = (ps - H) * (0.1f / 100.f) + 0.25f * cm;
    }
}

// ---------------------------------------------------------------- proj_out GEMM (split-N=4, 1 px/thread)
__global__ __launch_bounds__(256) void gemm_out_kernel(
        const float* __restrict__ w_out,
        const float* __restrict__ b_out,
        float* __restrict__ out) {
    __shared__ float s_wt[128 * 36];
    __shared__ float s_b[128];
    int tid = threadIdx.x;
    int kc = blockIdx.x & 3;
    int pg = blockIdx.x >> 2;
    int c0 = kc * 128;
    for (int i = tid; i < 128 * CD; i += 256) {
        int d = i >> 7, c = i & 127;
        s_wt[c * 36 + d] = w_out[d * DIMX + c0 + c];
    }
    if (tid < 128) s_b[tid] = b_out[c0 + tid];
    __syncthreads();

    int px = pg * 256 + tid;
    int b = px >> 12, pl = px & 4095;
    size_t o = (size_t)px * CD;

    unsigned long long Q[16];
#pragma unroll
    for (int k = 0; k < 8; k++) {
        float4 a = __ldg((const float4*)(g_r0 + o) + k);
        float4 r = ((const float4*)(g_r + o))[k];
        float qx = (r.x > 0.f) ? INV_SQRT32 : -INV_SQRT32;
        float qy = (r.y > 0.f) ? INV_SQRT32 : -INV_SQRT32;
        float qz = (r.z > 0.f) ? INV_SQRT32 : -INV_SQRT32;
        float qw = (r.w > 0.f) ? INV_SQRT32 : -INV_SQRT32;
        Q[2*k]   = pk2(a.x - r.x + qx, a.y - r.y + qy);
        Q[2*k+1] = pk2(a.z - r.z + qz, a.w - r.w + qw);
    }

    float* op = out + (size_t)b * (DIMX * HW) + (size_t)c0 * HW + pl;
#pragma unroll 2
    for (int c = 0; c < 128; c++) {
        const ulonglong2* wrow = (const ulonglong2*)(s_wt + c * 36);
        unsigned long long ae = 0, ao = 0;
#pragma unroll
        for (int r = 0; r < 8; r++) {
            ulonglong2 W = wrow[r];
            ae = fma2(Q[2*r],   W.x, ae);
            ao = fma2(Q[2*r+1], W.y, ao);
        }
        float lo, hi, sum;
        upk2(ae, lo, hi); sum = lo + hi;
        upk2(ao, lo, hi); sum += lo + hi;
        op[(size_t)c * HW] = sum + s_b[c];
    }
}

// ---------------------------------------------------------------- launch
extern "C" void kernel_launch(void* const* d_in, const int* in_sizes, int n_in,
                              void* d_out, int out_size) {
    const float* x     = (const float*)d_in[0];
    const float* w_in  = (const float*)d_in[1];
    const float* b_in  = (const float*)d_in[2];
    const float* w_out = (const float*)d_in[3];
    const float* b_out = (const float*)d_in[4];
    float* out = (float*)d_out;

    static const int sched[13] = {1,2,3,4,5,7,9,12,16,21,27,36,48};
    static const int SxT[7]    = {4,2,2,1,1,1,1};   // 16px x-chunks for ph 1,2,3,4,5,7,9

    init_kernel<<<370, 256>>>();
    gemm_in_kernel<<<1024, 256>>>(x, w_in);
    combine_kernel<<<2048, 256>>>(b_in);

    for (int s = 0; s < 12; s++) {
        int ph = sched[s];
        int ntok = B_ * ph * ph;
        int sliced = (s < 7);
        if (sliced) {
            int S = 64 / ph + 2;          // safe upper bound on region rows
            int Sx = SxT[s];
            int work = ntok * S * Sx;
            pool_small_kernel<<<(work + 7) / 8, 256>>>(s, S, Sx);
        } else {
            pool_big_kernel<<<(ntok + 7) / 8, 256>>>(s);   // uncapped grid
        }
        up_kernel<<<2048, 256>>>(s, sliced);
    }
    // s = 12: pool_big then fused up+loss13
    pool_big_kernel<<<(B_ * 48 * 48 + 7) / 8, 256>>>(12);
    up12_kernel<<<2048, 256>>>();

    if (out_size >= OUT_ELEMS + NSCALES)
        finalize_kernel<<<1, NSCALES * 32>>>(out + OUT_ELEMS);
    gemm_out_kernel<<<1024, 256>>>(w_out, b_out, out);
}